// round 13
// baseline (speedup 1.0000x reference)
#include <cuda_runtime.h>
#include <cuda_bf16.h>
#include <cstdint>
#include <math.h>

#define DIM    256
#define HEADS  8
#define HD     32
#define N1V    256
#define N2V    256
#define BTOT   256
#define NWIN   128
#define TBL    1575
#define MTOT   (BTOT * N1V)

typedef unsigned long long ull;

// ---------------- scratch (device globals; no allocation) ----------------
__device__ float d_qh [MTOT * DIM];              // scaled Q proj
__device__ float d_kvh[MTOT * 2 * DIM];          // K|V proj
__device__ float d_x  [MTOT * DIM];              // attention output
__device__ float d_biasF[HEADS * N1V * N2V];     // expanded rel-pos bias (2MB)

// ---------------- packed f32x2 helpers ----------------
__device__ __forceinline__ ull pack2(float x, float y) {
    ull r; asm("mov.b64 %0, {%1, %2};" : "=l"(r) : "f"(x), "f"(y)); return r;
}
__device__ __forceinline__ void unpack2(ull v, float& x, float& y) {
    asm("mov.b64 {%0, %1}, %2;" : "=f"(x), "=f"(y) : "l"(v));
}
__device__ __forceinline__ void ffma2(ull& d, ull a, ull b) {
    asm("fma.rn.f32x2 %0, %1, %2, %0;" : "+l"(d) : "l"(a), "l"(b));
}

// ---------------- FFMA2 NT SGEMM, double-buffered smem ---------------------
__global__ void __launch_bounds__(256) gemm_nt(
    const float* __restrict__ A, const float* __restrict__ B,
    const float* __restrict__ bias, float* __restrict__ C,
    int M, int N, int K, float alpha)
{
    __shared__ float As[2][16][132];
    __shared__ float Bs[2][16][132];
    const int m0  = blockIdx.y * 128;
    const int n0  = blockIdx.x * 128;
    const int tid = threadIdx.x;
    const int tr  = tid >> 4;
    const int tc  = tid & 15;

    int lr[2], lc[2];
#pragma unroll
    for (int i = 0; i < 2; i++) {
        int li = tid + i * 256;
        lr[i] = li >> 2;
        lc[i] = (li & 3) << 2;
    }

    ull acc2[8][4];
#pragma unroll
    for (int i = 0; i < 8; i++)
#pragma unroll
        for (int j = 0; j < 4; j++) acc2[i][j] = 0ull;

    const int NT = K >> 4;

#pragma unroll
    for (int i = 0; i < 2; i++) {
        float4 va = *(const float4*)(A + (size_t)(m0 + lr[i]) * K + lc[i]);
        As[0][lc[i] + 0][lr[i]] = va.x; As[0][lc[i] + 1][lr[i]] = va.y;
        As[0][lc[i] + 2][lr[i]] = va.z; As[0][lc[i] + 3][lr[i]] = va.w;
        float4 vb = *(const float4*)(B + (size_t)(n0 + lr[i]) * K + lc[i]);
        Bs[0][lc[i] + 0][lr[i]] = vb.x; Bs[0][lc[i] + 1][lr[i]] = vb.y;
        Bs[0][lc[i] + 2][lr[i]] = vb.z; Bs[0][lc[i] + 3][lr[i]] = vb.w;
    }
    __syncthreads();

#pragma unroll 1
    for (int kt = 0; kt < NT; kt++) {
        const int cur = kt & 1;
        float4 na[2], nb[2];
        const bool more = (kt + 1 < NT);
        if (more) {
            const int k0 = (kt + 1) << 4;
#pragma unroll
            for (int i = 0; i < 2; i++) {
                na[i] = *(const float4*)(A + (size_t)(m0 + lr[i]) * K + k0 + lc[i]);
                nb[i] = *(const float4*)(B + (size_t)(n0 + lr[i]) * K + k0 + lc[i]);
            }
        }
#pragma unroll
        for (int kk = 0; kk < 16; kk++) {
            float4 a0 = *(const float4*)&As[cur][kk][tr * 8];
            float4 a1 = *(const float4*)&As[cur][kk][tr * 8 + 4];
            ull b2[4];
#pragma unroll
            for (int j = 0; j < 4; j++)
                b2[j] = *(const ull*)&Bs[cur][kk][tc * 8 + 2 * j];
            ull ad[8];
            ad[0] = pack2(a0.x, a0.x); ad[1] = pack2(a0.y, a0.y);
            ad[2] = pack2(a0.z, a0.z); ad[3] = pack2(a0.w, a0.w);
            ad[4] = pack2(a1.x, a1.x); ad[5] = pack2(a1.y, a1.y);
            ad[6] = pack2(a1.z, a1.z); ad[7] = pack2(a1.w, a1.w);
#pragma unroll
            for (int i = 0; i < 8; i++)
#pragma unroll
                for (int j = 0; j < 4; j++)
                    ffma2(acc2[i][j], ad[i], b2[j]);
        }
        if (more) {
            const int nxt = cur ^ 1;
#pragma unroll
            for (int i = 0; i < 2; i++) {
                As[nxt][lc[i] + 0][lr[i]] = na[i].x; As[nxt][lc[i] + 1][lr[i]] = na[i].y;
                As[nxt][lc[i] + 2][lr[i]] = na[i].z; As[nxt][lc[i] + 3][lr[i]] = na[i].w;
                Bs[nxt][lc[i] + 0][lr[i]] = nb[i].x; Bs[nxt][lc[i] + 1][lr[i]] = nb[i].y;
                Bs[nxt][lc[i] + 2][lr[i]] = nb[i].z; Bs[nxt][lc[i] + 3][lr[i]] = nb[i].w;
            }
            __syncthreads();
        }
    }

#pragma unroll
    for (int i = 0; i < 8; i++) {
        int r = m0 + tr * 8 + i;
#pragma unroll
        for (int j = 0; j < 4; j++) {
            int c = n0 + tc * 8 + 2 * j;
            float x, y;
            unpack2(acc2[i][j], x, y);
            float2 v;
            v.x = alpha * (x + bias[c]);
            v.y = alpha * (y + bias[c + 1]);
            *(float2*)(C + (size_t)r * N + c) = v;
        }
    }
}

// ---------------- rel-pos bias expansion: biasF[h][q][k] -------------------
__global__ void __launch_bounds__(256) bias_pre(
    const float* __restrict__ btab_g, const int* __restrict__ rel,
    float* __restrict__ biasF)
{
    int idx = blockIdx.x * 256 + threadIdx.x;
    int ri  = rel[idx] * HEADS;
#pragma unroll
    for (int h = 0; h < HEADS; h++)
        biasF[h * (N1V * N2V) + idx] = btab_g[ri + h];
}

// ---------------- attention v6: 32-query tiles, 3 blocks/SM ----------------
// grid (8 qtiles of 32, HEADS, BTOT), 256 threads.
// QK: thread (qg=tid>>4 -> 2 queries, kg=tid&15 -> 16 keys kj=16j+kg).
// PV: thread (qi=tid>>3 -> 1 query, dg=tid&7 -> 4 dims).
#define SK 36
#define SQ 36
#define SP 260
#define QT 32                                    // queries per block
#define KV_OFF 0
#define PB_OFF (256 * SK)                        // 9216 floats
#define ATTN_SMEM_FLOATS (PB_OFF + QT * SP)      // 17536 floats
#define ATTN_SMEM_BYTES (ATTN_SMEM_FLOATS * 4)   // 70144 B -> 3 blocks/SM

__global__ void __launch_bounds__(256, 3) attn_kernel(
    const float* __restrict__ qh, const float* __restrict__ kvh,
    const float* __restrict__ mask, const float* __restrict__ biasF,
    float* __restrict__ xout)
{
    extern __shared__ float smem[];
    float* Ks = smem + KV_OFF;     // K tile, later V tile
    float* Pb = smem + PB_OFF;     // Qs alias, then mask+bias stage, then P
    float* Qs = Pb;

    const int tid = threadIdx.x;
    const int qg  = tid >> 4;      // 0..15
    const int kg  = tid & 15;      // 0..15
    const int q0  = blockIdx.x * QT;
    const int h   = blockIdx.y;
    const int b   = blockIdx.z;
    const int w   = b & (NWIN - 1);
    const int qi0 = qg * 2;

    // ---- load Q (32x32, into Pb head) and K (256x32) ----
    {
        const float* qbase = qh + ((size_t)(b * N1V + q0)) * DIM + h * HD;
        {
            int r  = tid >> 3;               // 0..31
            int c4 = (tid & 7) * 4;
            *(float4*)&Qs[r * SQ + c4] =
                *(const float4*)(qbase + (size_t)r * DIM + c4);
        }
        const float* kbase = kvh + ((size_t)b * N2V) * (2 * DIM) + h * HD;
#pragma unroll
        for (int i = 0; i < 8; i++) {
            int li = tid + i * 256;
            int r  = li >> 3;
            int c4 = (li & 7) * 4;
            *(float4*)&Ks[r * SK + c4] =
                *(const float4*)(kbase + (size_t)r * (2 * DIM) + c4);
        }
    }
    __syncthreads();

    // ---- QK: s[2][16], 32 independent FMA chains ----
    float s[2][16];
#pragma unroll
    for (int i = 0; i < 2; i++)
#pragma unroll
        for (int j = 0; j < 16; j++) s[i][j] = 0.f;

#pragma unroll 2
    for (int c4 = 0; c4 < 8; c4++) {
        float q[2][4];
#pragma unroll
        for (int i = 0; i < 2; i++) {
            float4 v = *(const float4*)&Qs[(qi0 + i) * SQ + c4 * 4];
            q[i][0] = v.x; q[i][1] = v.y; q[i][2] = v.z; q[i][3] = v.w;
        }
#pragma unroll
        for (int j = 0; j < 16; j++) {
            float4 kv = *(const float4*)&Ks[(16 * j + kg) * SK + c4 * 4];
#pragma unroll
            for (int i = 0; i < 2; i++) {
                s[i][j] = fmaf(q[i][0], kv.x, s[i][j]);
                s[i][j] = fmaf(q[i][1], kv.y, s[i][j]);
                s[i][j] = fmaf(q[i][2], kv.z, s[i][j]);
                s[i][j] = fmaf(q[i][3], kv.w, s[i][j]);
            }
        }
    }
    __syncthreads();   // Q/K reads done -> V may overwrite Ks, stage may use Pb

    // ---- load V (over K) and mask+bias stage (into Pb) ----
    {
        const float* vbase = kvh + ((size_t)b * N2V) * (2 * DIM) + DIM + h * HD;
#pragma unroll
        for (int i = 0; i < 8; i++) {
            int li = tid + i * 256;
            int r  = li >> 3;
            int c4 = (li & 7) * 4;
            *(float4*)&Ks[r * SK + c4] =
                *(const float4*)(vbase + (size_t)r * (2 * DIM) + c4);
        }
        const float* maskb = mask  + ((size_t)(w * N1V + q0)) * N2V;
        const float* biasb = biasF + ((size_t)(h * N1V + q0)) * N2V;
#pragma unroll
        for (int i = 0; i < 8; i++) {
            int li = tid + i * 256;          // 0..2047 float4 (32x256/4)
            int r  = li >> 6;
            int c4 = (li & 63) * 4;
            float4 mv = *(const float4*)(maskb + (size_t)r * N2V + c4);
            float4 bv = *(const float4*)(biasb + (size_t)r * N2V + c4);
            float4 sv;
            sv.x = mv.x + bv.x; sv.y = mv.y + bv.y;
            sv.z = mv.z + bv.z; sv.w = mv.w + bv.w;
            *(float4*)&Pb[r * SP + c4] = sv;
        }
    }
    __syncthreads();

    // ---- add mask+bias; softmax via bfly over kg lane bits ----
#pragma unroll
    for (int i = 0; i < 2; i++)
#pragma unroll
        for (int j = 0; j < 16; j++)
            s[i][j] += Pb[(qi0 + i) * SP + 16 * j + kg];

    float linv[2];
#pragma unroll
    for (int i = 0; i < 2; i++) {
        float mx = s[i][0];
#pragma unroll
        for (int j = 1; j < 16; j++) mx = fmaxf(mx, s[i][j]);
        mx = fmaxf(mx, __shfl_xor_sync(0xFFFFFFFFu, mx, 1));
        mx = fmaxf(mx, __shfl_xor_sync(0xFFFFFFFFu, mx, 2));
        mx = fmaxf(mx, __shfl_xor_sync(0xFFFFFFFFu, mx, 4));
        mx = fmaxf(mx, __shfl_xor_sync(0xFFFFFFFFu, mx, 8));
        float ls = 0.f;
#pragma unroll
        for (int j = 0; j < 16; j++) {
            float e = __expf(s[i][j] - mx);
            s[i][j] = e;
            ls += e;
        }
        ls += __shfl_xor_sync(0xFFFFFFFFu, ls, 1);
        ls += __shfl_xor_sync(0xFFFFFFFFu, ls, 2);
        ls += __shfl_xor_sync(0xFFFFFFFFu, ls, 4);
        ls += __shfl_xor_sync(0xFFFFFFFFu, ls, 8);
        linv[i] = 1.0f / ls;
    }
    __syncthreads();   // stage reads done -> overwrite Pb with P

    // ---- store P (1/l folded) ----
#pragma unroll
    for (int i = 0; i < 2; i++)
#pragma unroll
        for (int j = 0; j < 16; j++)
            Pb[(qi0 + i) * SP + 16 * j + kg] = s[i][j] * linv[i];
    __syncthreads();

    // ---- PV: thread (qi, dg) -> 1 query x dims {4dg..4dg+3} ----
    const int qi = tid >> 3;       // 0..31
    const int dg = tid & 7;        // 0..7
    float o[4] = {0.f, 0.f, 0.f, 0.f};

#pragma unroll 4
    for (int k4 = 0; k4 < 64; k4++) {
        float4 pq = *(const float4*)&Pb[qi * SP + k4 * 4];
        float pa[4] = {pq.x, pq.y, pq.z, pq.w};
#pragma unroll
        for (int kk = 0; kk < 4; kk++) {
            float4 vv = *(const float4*)&Ks[(k4 * 4 + kk) * SK + 4 * dg];
            o[0] = fmaf(pa[kk], vv.x, o[0]);
            o[1] = fmaf(pa[kk], vv.y, o[1]);
            o[2] = fmaf(pa[kk], vv.z, o[2]);
            o[3] = fmaf(pa[kk], vv.w, o[3]);
        }
    }

    // ---- write O: float4 per thread ----
    {
        float4 v; v.x = o[0]; v.y = o[1]; v.z = o[2]; v.w = o[3];
        *(float4*)(xout + ((size_t)(b * N1V + q0 + qi)) * DIM
                   + h * HD + 4 * dg) = v;
    }
}

// ---------------- launch ----------------
extern "C" void kernel_launch(void* const* d_in, const int* in_sizes, int n_in,
                              void* d_out, int out_size)
{
    const float* q    = (const float*)d_in[0];
    const float* kv   = (const float*)d_in[1];
    const float* mask = (const float*)d_in[2];
    const float* Wq   = (const float*)d_in[3];
    const float* bq   = (const float*)d_in[4];
    const float* Wkv  = (const float*)d_in[5];
    const float* bkv  = (const float*)d_in[6];
    const float* btab = (const float*)d_in[7];
    const float* Wp   = (const float*)d_in[8];
    const float* bp   = (const float*)d_in[9];
    const int*   rel  = (const int*)d_in[10];
    float* out = (float*)d_out;

    static float* qh  = nullptr;
    static float* kvh = nullptr;
    static float* xb  = nullptr;
    static float* bF  = nullptr;
    if (!qh) {
        cudaGetSymbolAddress((void**)&qh,  d_qh);
        cudaGetSymbolAddress((void**)&kvh, d_kvh);
        cudaGetSymbolAddress((void**)&xb,  d_x);
        cudaGetSymbolAddress((void**)&bF,  d_biasF);
        cudaFuncSetAttribute(attn_kernel,
                             cudaFuncAttributeMaxDynamicSharedMemorySize,
                             ATTN_SMEM_BYTES);
    }

    const int M = MTOT;
    const float scale = 0.17677669529663687f;       // 1/sqrt(32)

    bias_pre<<<N1V * N2V / 256, 256>>>(btab, rel, bF);
    gemm_nt<<<dim3(DIM / 128, M / 128), 256>>>(q, Wq, bq, qh, M, DIM, DIM, scale);
    gemm_nt<<<dim3((2 * DIM) / 128, M / 128), 256>>>(kv, Wkv, bkv, kvh, M, 2 * DIM, DIM, 1.f);
    attn_kernel<<<dim3(8, HEADS, BTOT), 256, ATTN_SMEM_BYTES>>>(qh, kvh, mask, bF, xb);
    gemm_nt<<<dim3(DIM / 128, M / 128), 256>>>(xb, Wp, bp, out, M, DIM, DIM, 1.f);
}

// round 14
// speedup vs baseline: 1.4441x; 1.4441x over previous
#include <cuda_runtime.h>
#include <cuda_bf16.h>
#include <cstdint>
#include <math.h>

#define DIM    256
#define HEADS  8
#define HD     32
#define N1V    256
#define N2V    256
#define BTOT   256
#define NWIN   128
#define TBL    1575
#define MTOT   (BTOT * N1V)

typedef unsigned long long ull;

// ---------------- scratch (device globals; no allocation) ----------------
__device__ float d_qh [MTOT * DIM];              // scaled Q proj
__device__ float d_kvh[MTOT * 2 * DIM];          // K|V proj
__device__ float d_x  [MTOT * DIM];              // attention output
__device__ float d_biasF[HEADS * N1V * N2V];     // expanded rel-pos bias (2MB)

// ---------------- packed f32x2 helpers ----------------
__device__ __forceinline__ ull pack2(float x, float y) {
    ull r; asm("mov.b64 %0, {%1, %2};" : "=l"(r) : "f"(x), "f"(y)); return r;
}
__device__ __forceinline__ void unpack2(ull v, float& x, float& y) {
    asm("mov.b64 {%0, %1}, %2;" : "=f"(x), "=f"(y) : "l"(v));
}
__device__ __forceinline__ void ffma2(ull& d, ull a, ull b) {
    asm("fma.rn.f32x2 %0, %1, %2, %0;" : "+l"(d) : "l"(a), "l"(b));
}

// ---------------- FFMA2 NT SGEMM, 128x64 tile, 3 blocks/SM -----------------
// C = alpha * (A @ B^T + bias); A:[M,K], B:[N,K] row-major.
// 256 threads, thread tile 8m x 4n; accumulator lanes = adjacent M rows, so
// A pairs reinterpret directly from the smem float4 (only b needs dup-packs).
__global__ void __launch_bounds__(256, 3) gemm_nt(
    const float* __restrict__ A, const float* __restrict__ B,
    const float* __restrict__ bias, float* __restrict__ C,
    int M, int N, int K, float alpha)
{
    __shared__ float As[2][16][132];
    __shared__ float Bs[2][16][68];
    const int m0  = blockIdx.y * 128;
    const int n0  = blockIdx.x * 64;
    const int tid = threadIdx.x;
    const int tr  = tid >> 4;      // 0..15 -> rows tr*8 .. tr*8+7
    const int tc  = tid & 15;      // 0..15 -> cols tc*4 .. tc*4+3

    // staging coords: A 2 float4/thread, B 1 float4/thread
    int lrA[2], lcA[2];
#pragma unroll
    for (int i = 0; i < 2; i++) {
        int li = tid + i * 256;
        lrA[i] = li >> 2;              // 0..127
        lcA[i] = (li & 3) << 2;        // 0,4,8,12
    }
    const int lrB = tid >> 2;          // 0..63
    const int lcB = (tid & 3) << 2;    // 0,4,8,12

    ull acc2[4][4];
#pragma unroll
    for (int i = 0; i < 4; i++)
#pragma unroll
        for (int j = 0; j < 4; j++) acc2[i][j] = 0ull;

    const int NT = K >> 4;

    // prologue: tile 0
#pragma unroll
    for (int i = 0; i < 2; i++) {
        float4 va = *(const float4*)(A + (size_t)(m0 + lrA[i]) * K + lcA[i]);
        As[0][lcA[i] + 0][lrA[i]] = va.x; As[0][lcA[i] + 1][lrA[i]] = va.y;
        As[0][lcA[i] + 2][lrA[i]] = va.z; As[0][lcA[i] + 3][lrA[i]] = va.w;
    }
    {
        float4 vb = *(const float4*)(B + (size_t)(n0 + lrB) * K + lcB);
        Bs[0][lcB + 0][lrB] = vb.x; Bs[0][lcB + 1][lrB] = vb.y;
        Bs[0][lcB + 2][lrB] = vb.z; Bs[0][lcB + 3][lrB] = vb.w;
    }
    __syncthreads();

#pragma unroll 1
    for (int kt = 0; kt < NT; kt++) {
        const int cur = kt & 1;
        float4 na[2], nb;
        const bool more = (kt + 1 < NT);
        if (more) {
            const int k0 = (kt + 1) << 4;
#pragma unroll
            for (int i = 0; i < 2; i++)
                na[i] = *(const float4*)(A + (size_t)(m0 + lrA[i]) * K + k0 + lcA[i]);
            nb = *(const float4*)(B + (size_t)(n0 + lrB) * K + k0 + lcB);
        }
#pragma unroll
        for (int kk = 0; kk < 16; kk++) {
            float4 a04 = *(const float4*)&As[cur][kk][tr * 8];
            float4 a48 = *(const float4*)&As[cur][kk][tr * 8 + 4];
            float4 bq  = *(const float4*)&Bs[cur][kk][tc * 4];
            ull ap[4];
            ap[0] = pack2(a04.x, a04.y); ap[1] = pack2(a04.z, a04.w);
            ap[2] = pack2(a48.x, a48.y); ap[3] = pack2(a48.z, a48.w);
            ull b2[4];
            b2[0] = pack2(bq.x, bq.x); b2[1] = pack2(bq.y, bq.y);
            b2[2] = pack2(bq.z, bq.z); b2[3] = pack2(bq.w, bq.w);
#pragma unroll
            for (int mi = 0; mi < 4; mi++)
#pragma unroll
                for (int n = 0; n < 4; n++)
                    ffma2(acc2[mi][n], ap[mi], b2[n]);
        }
        if (more) {
            const int nxt = cur ^ 1;
#pragma unroll
            for (int i = 0; i < 2; i++) {
                As[nxt][lcA[i] + 0][lrA[i]] = na[i].x; As[nxt][lcA[i] + 1][lrA[i]] = na[i].y;
                As[nxt][lcA[i] + 2][lrA[i]] = na[i].z; As[nxt][lcA[i] + 3][lrA[i]] = na[i].w;
            }
            Bs[nxt][lcB + 0][lrB] = nb.x; Bs[nxt][lcB + 1][lrB] = nb.y;
            Bs[nxt][lcB + 2][lrB] = nb.z; Bs[nxt][lcB + 3][lrB] = nb.w;
            __syncthreads();
        }
    }

    // epilogue: acc2[mi][n] lanes = rows (tr*8+2mi, tr*8+2mi+1), col tc*4+n
    float b4[4];
#pragma unroll
    for (int n = 0; n < 4; n++) b4[n] = bias[n0 + tc * 4 + n];
#pragma unroll
    for (int mi = 0; mi < 4; mi++) {
        int r = m0 + tr * 8 + 2 * mi;
        float4 v0, v1;
        float x, y;
        unpack2(acc2[mi][0], x, y); v0.x = alpha * (x + b4[0]); v1.x = alpha * (y + b4[0]);
        unpack2(acc2[mi][1], x, y); v0.y = alpha * (x + b4[1]); v1.y = alpha * (y + b4[1]);
        unpack2(acc2[mi][2], x, y); v0.z = alpha * (x + b4[2]); v1.z = alpha * (y + b4[2]);
        unpack2(acc2[mi][3], x, y); v0.w = alpha * (x + b4[3]); v1.w = alpha * (y + b4[3]);
        *(float4*)(C + (size_t)r * N + n0 + tc * 4)       = v0;
        *(float4*)(C + (size_t)(r + 1) * N + n0 + tc * 4) = v1;
    }
}

// ---------------- rel-pos bias expansion: biasF[h][q][k] -------------------
__global__ void __launch_bounds__(256) bias_pre(
    const float* __restrict__ btab_g, const int* __restrict__ rel,
    float* __restrict__ biasF)
{
    int idx = blockIdx.x * 256 + threadIdx.x;
    int ri  = rel[idx] * HEADS;
#pragma unroll
    for (int h = 0; h < HEADS; h++)
        biasF[h * (N1V * N2V) + idx] = btab_g[ri + h];
}

// ---------------- attention v4 (R10, 594us measured): 2 blocks/SM ----------
#define SK 36
#define SQ 36
#define SP 260
#define KV_OFF 0
#define PB_OFF (256 * SK)                        // 9216 floats
#define ATTN_SMEM_FLOATS (PB_OFF + 64 * SP)      // 25856 floats
#define ATTN_SMEM_BYTES (ATTN_SMEM_FLOATS * 4)   // 103424 B -> 2 blocks/SM

__global__ void __launch_bounds__(256, 2) attn_kernel(
    const float* __restrict__ qh, const float* __restrict__ kvh,
    const float* __restrict__ mask, const float* __restrict__ biasF,
    float* __restrict__ xout)
{
    extern __shared__ float smem[];
    float* Ks = smem + KV_OFF;     // K tile, later V tile
    float* Pb = smem + PB_OFF;     // Qs alias, then mask+bias stage, then P
    float* Qs = Pb;

    const int tid = threadIdx.x;
    const int qg  = tid >> 4;
    const int kg  = tid & 15;
    const int q0  = blockIdx.x * 64;
    const int h   = blockIdx.y;
    const int b   = blockIdx.z;
    const int w   = b & (NWIN - 1);
    const int qi0 = qg * 4;

    // ---- load Q (64x32, into Pb head) and K (256x32) ----
    {
        const float* qbase = qh + ((size_t)(b * N1V + q0)) * DIM + h * HD;
#pragma unroll
        for (int i = 0; i < 2; i++) {
            int li = tid + i * 256;
            int r  = li >> 3;
            int c4 = (li & 7) * 4;
            *(float4*)&Qs[r * SQ + c4] =
                *(const float4*)(qbase + (size_t)r * DIM + c4);
        }
        const float* kbase = kvh + ((size_t)b * N2V) * (2 * DIM) + h * HD;
#pragma unroll
        for (int i = 0; i < 8; i++) {
            int li = tid + i * 256;
            int r  = li >> 3;
            int c4 = (li & 7) * 4;
            *(float4*)&Ks[r * SK + c4] =
                *(const float4*)(kbase + (size_t)r * (2 * DIM) + c4);
        }
    }
    __syncthreads();

    // ---- QK: s[4][16], 64 independent FMA chains ----
    float s[4][16];
#pragma unroll
    for (int i = 0; i < 4; i++)
#pragma unroll
        for (int j = 0; j < 16; j++) s[i][j] = 0.f;

#pragma unroll 2
    for (int c4 = 0; c4 < 8; c4++) {
        float q[4][4];
#pragma unroll
        for (int i = 0; i < 4; i++) {
            float4 v = *(const float4*)&Qs[(qi0 + i) * SQ + c4 * 4];
            q[i][0] = v.x; q[i][1] = v.y; q[i][2] = v.z; q[i][3] = v.w;
        }
#pragma unroll
        for (int j = 0; j < 16; j++) {
            float4 kv = *(const float4*)&Ks[(16 * j + kg) * SK + c4 * 4];
#pragma unroll
            for (int i = 0; i < 4; i++) {
                s[i][j] = fmaf(q[i][0], kv.x, s[i][j]);
                s[i][j] = fmaf(q[i][1], kv.y, s[i][j]);
                s[i][j] = fmaf(q[i][2], kv.z, s[i][j]);
                s[i][j] = fmaf(q[i][3], kv.w, s[i][j]);
            }
        }
    }
    __syncthreads();   // Q/K reads done -> V may overwrite Ks, stage may use Pb

    // ---- load V (over K) and mask+bias stage (into Pb) ----
    {
        const float* vbase = kvh + ((size_t)b * N2V) * (2 * DIM) + DIM + h * HD;
#pragma unroll
        for (int i = 0; i < 8; i++) {
            int li = tid + i * 256;
            int r  = li >> 3;
            int c4 = (li & 7) * 4;
            *(float4*)&Ks[r * SK + c4] =
                *(const float4*)(vbase + (size_t)r * (2 * DIM) + c4);
        }
        const float* maskb = mask  + ((size_t)(w * N1V + q0)) * N2V;
        const float* biasb = biasF + ((size_t)(h * N1V + q0)) * N2V;
#pragma unroll
        for (int i = 0; i < 16; i++) {
            int li = tid + i * 256;
            int r  = li >> 6;
            int c4 = (li & 63) * 4;
            float4 mv = *(const float4*)(maskb + (size_t)r * N2V + c4);
            float4 bv = *(const float4*)(biasb + (size_t)r * N2V + c4);
            float4 sv;
            sv.x = mv.x + bv.x; sv.y = mv.y + bv.y;
            sv.z = mv.z + bv.z; sv.w = mv.w + bv.w;
            *(float4*)&Pb[r * SP + c4] = sv;
        }
    }
    __syncthreads();

    // ---- add mask+bias; softmax via bfly over kg lane bits ----
#pragma unroll
    for (int i = 0; i < 4; i++)
#pragma unroll
        for (int j = 0; j < 16; j++)
            s[i][j] += Pb[(qi0 + i) * SP + 16 * j + kg];

    float linv[4];
#pragma unroll
    for (int i = 0; i < 4; i++) {
        float mx = s[i][0];
#pragma unroll
        for (int j = 1; j < 16; j++) mx = fmaxf(mx, s[i][j]);
        mx = fmaxf(mx, __shfl_xor_sync(0xFFFFFFFFu, mx, 1));
        mx = fmaxf(mx, __shfl_xor_sync(0xFFFFFFFFu, mx, 2));
        mx = fmaxf(mx, __shfl_xor_sync(0xFFFFFFFFu, mx, 4));
        mx = fmaxf(mx, __shfl_xor_sync(0xFFFFFFFFu, mx, 8));
        float ls = 0.f;
#pragma unroll
        for (int j = 0; j < 16; j++) {
            float e = __expf(s[i][j] - mx);
            s[i][j] = e;
            ls += e;
        }
        ls += __shfl_xor_sync(0xFFFFFFFFu, ls, 1);
        ls += __shfl_xor_sync(0xFFFFFFFFu, ls, 2);
        ls += __shfl_xor_sync(0xFFFFFFFFu, ls, 4);
        ls += __shfl_xor_sync(0xFFFFFFFFu, ls, 8);
        linv[i] = 1.0f / ls;
    }
    __syncthreads();   // stage reads done -> overwrite Pb with P

    // ---- store P (1/l folded) ----
#pragma unroll
    for (int i = 0; i < 4; i++)
#pragma unroll
        for (int j = 0; j < 16; j++)
            Pb[(qi0 + i) * SP + 16 * j + kg] = s[i][j] * linv[i];
    __syncthreads();

    // ---- PV: thread (qg, kg) -> 4 queries x dims {2kg, 2kg+1} ----
    float o[4][2];
#pragma unroll
    for (int i = 0; i < 4; i++) { o[i][0] = 0.f; o[i][1] = 0.f; }

#pragma unroll 4
    for (int k4 = 0; k4 < 64; k4++) {
        float p[4][4];
#pragma unroll
        for (int i = 0; i < 4; i++) {
            float4 v = *(const float4*)&Pb[(qi0 + i) * SP + k4 * 4];
            p[i][0] = v.x; p[i][1] = v.y; p[i][2] = v.z; p[i][3] = v.w;
        }
#pragma unroll
        for (int kk = 0; kk < 4; kk++) {
            float2 vv = *(const float2*)&Ks[(k4 * 4 + kk) * SK + 2 * kg];
#pragma unroll
            for (int i = 0; i < 4; i++) {
                o[i][0] = fmaf(p[i][kk], vv.x, o[i][0]);
                o[i][1] = fmaf(p[i][kk], vv.y, o[i][1]);
            }
        }
    }

    // ---- write O ----
#pragma unroll
    for (int i = 0; i < 4; i++) {
        float2 v; v.x = o[i][0]; v.y = o[i][1];
        *(float2*)(xout + ((size_t)(b * N1V + q0 + qi0 + i)) * DIM
                   + h * HD + 2 * kg) = v;
    }
}

// ---------------- launch ----------------
extern "C" void kernel_launch(void* const* d_in, const int* in_sizes, int n_in,
                              void* d_out, int out_size)
{
    const float* q    = (const float*)d_in[0];
    const float* kv   = (const float*)d_in[1];
    const float* mask = (const float*)d_in[2];
    const float* Wq   = (const float*)d_in[3];
    const float* bq   = (const float*)d_in[4];
    const float* Wkv  = (const float*)d_in[5];
    const float* bkv  = (const float*)d_in[6];
    const float* btab = (const float*)d_in[7];
    const float* Wp   = (const float*)d_in[8];
    const float* bp   = (const float*)d_in[9];
    const int*   rel  = (const int*)d_in[10];
    float* out = (float*)d_out;

    static float* qh  = nullptr;
    static float* kvh = nullptr;
    static float* xb  = nullptr;
    static float* bF  = nullptr;
    if (!qh) {
        cudaGetSymbolAddress((void**)&qh,  d_qh);
        cudaGetSymbolAddress((void**)&kvh, d_kvh);
        cudaGetSymbolAddress((void**)&xb,  d_x);
        cudaGetSymbolAddress((void**)&bF,  d_biasF);
        cudaFuncSetAttribute(attn_kernel,
                             cudaFuncAttributeMaxDynamicSharedMemorySize,
                             ATTN_SMEM_BYTES);
    }

    const int M = MTOT;
    const float scale = 0.17677669529663687f;       // 1/sqrt(32)

    bias_pre<<<N1V * N2V / 256, 256>>>(btab, rel, bF);
    gemm_nt<<<dim3(DIM / 64, M / 128), 256>>>(q, Wq, bq, qh, M, DIM, DIM, scale);
    gemm_nt<<<dim3((2 * DIM) / 64, M / 128), 256>>>(kv, Wkv, bkv, kvh, M, 2 * DIM, DIM, 1.f);
    attn_kernel<<<dim3(4, HEADS, BTOT), 256, ATTN_SMEM_BYTES>>>(qh, kvh, mask, bF, xb);
    gemm_nt<<<dim3(DIM / 64, M / 128), 256>>>(xb, Wp, bp, out, M, DIM, DIM, 1.f);
}